// round 14
// baseline (speedup 1.0000x reference)
#include <cuda_runtime.h>
#include <cuda_fp16.h>
#include <math.h>

#define NB   8
#define GH   224
#define GW   224
#define RAD  3
#define TW   32
#define TH   32
#define HC   38
#define HR   38
#define NHALO (HR * HC)  // 1444
#define NPIX (NB * GH * GW)          // 401408
#define QW   12
#define LOG2E 1.4426950408889634f
#define NSTAGE_BLKS 392              // 7 x 7 x 8 tiles
#define NQ_BLKS     1568             // NPIX / 256
#define NLIN_BLKS   972              // 7776 outputs / 8 warps
#define NBIC1_BLKS  378              // 24*18*224 / 256

// scratch (no allocations allowed)
__device__ float g_f0[NB * 972];
__device__ __align__(16) float g_tmp[24 * 18 * 224];
__device__ __align__(16) float4 g_bufA[NPIX];   // interleaved {f0,f1,f2,_}
__device__ __align__(16) float4 g_bufB[NPIX];
__device__ unsigned int g_q[(size_t)4 * NPIX * QW];
__device__ int g_w2q[4 * 32 * 8];
__device__ float g_w2s[4 * 32];
__device__ float g_us[4];
__device__ float4 g_lutw[224];
__device__ int4   g_luti[224];

__device__ __forceinline__ int reflect224(int v) {
    if (v < 0) v = -v;
    if (v > 223) v = 446 - v;
    return v;
}

__device__ __forceinline__ float cubw(float d) {
    d = fabsf(d);
    if (d <= 1.f) return (1.25f * d - 2.25f) * d * d + 1.f;
    if (d < 2.f)  return ((-0.75f * d + 3.75f) * d - 6.f) * d + 3.f;
    return 0.f;
}

__device__ __forceinline__ int pack4(float a, float b, float c, float d, float rs) {
    int i0 = __float2int_rn(a * rs);
    int i1 = __float2int_rn(b * rs);
    int i2 = __float2int_rn(c * rs);
    int i3 = __float2int_rn(d * rs);
    return (i0 & 255) | ((i1 & 255) << 8) | ((i2 & 255) << 16) | (i3 << 24);
}

// ---------------------------------------------------------------------------
// init roles (run inside L1 launch as extra blocks)
// ---------------------------------------------------------------------------
__device__ void init_lut_block(const float* w1s_, const float* b1s_, int tid) {
    if (tid < 224) {
        float fx = (tid + 0.5f) * (18.f / 224.f) - 0.5f;
        int x0 = (int)floorf(fx);
        float tx = fx - x0;
        float4 w; int4 ix;
        w.x = cubw(tx + 1.f); w.y = cubw(tx); w.z = cubw(tx - 1.f); w.w = cubw(tx - 2.f);
        ix.x = min(max(x0 - 1, 0), 17); ix.y = min(max(x0, 0), 17);
        ix.z = min(max(x0 + 1, 0), 17); ix.w = min(max(x0 + 2, 0), 17);
        g_lutw[tid] = w; g_luti[tid] = ix;
    } else if (tid >= 224 && tid < 228) {
        int s = tid - 224;
        float ub = 0.2f;
        for (int k = 0; k < 32; k++) {
            float bnd = fabsf(b1s_[s * 32 + k]);
            for (int c = 0; c < 3; c++) bnd += fabsf(w1s_[s * 96 + k * 3 + c]);
            ub = fmaxf(ub, bnd);
        }
        g_us[s] = ub;
    }
}

__device__ void init_w2_block(const float* w2s_, int tid) {
    if (tid >= 128) return;
    int r = tid;                       // stage*32 + row
    const float* row = w2s_ + r * 32;
    float mx = 1e-12f;
    #pragma unroll
    for (int k = 0; k < 32; k++) mx = fmaxf(mx, fabsf(row[k]));
    float rs = 127.f / mx;
    #pragma unroll
    for (int w = 0; w < 8; w++)
        g_w2q[r * 8 + w] = pack4(row[4 * w], row[4 * w + 1], row[4 * w + 2], row[4 * w + 3], rs);
    g_w2s[r] = mx * (1.f / 127.f);
}

// ---------------------------------------------------------------------------
// qproj block: 256 px, int8 dp4a matvec
// ---------------------------------------------------------------------------
__device__ __forceinline__ void qproj_block(
    int s, int qbid, int tid,
    const float* __restrict__ guid,
    const float* __restrict__ w1s, const float* __restrict__ b1s,
    const float* __restrict__ b2s)
{
    __shared__ float sw1[96];
    __shared__ float sb1[32];
    __shared__ float sb2[32];
    __shared__ float ssc[32];
    __shared__ int sw2q[32][8];

    if (tid < 96) sw1[tid] = w1s[s * 96 + tid];
    if (tid < 32) {
        sb1[tid] = b1s[s * 32 + tid];
        sb2[tid] = b2s[s * 32 + tid];
        ssc[tid] = g_w2s[s * 32 + tid];
    }
    sw2q[tid >> 3][tid & 7] = g_w2q[(s * 32 + (tid >> 3)) * 8 + (tid & 7)];
    __syncthreads();

    const float uscale = g_us[s];
    const float ru = 127.f / uscale;
    const float us_ = uscale * (1.f / 127.f);

    const int pix = qbid * 256 + tid;
    const int b = pix / (GH * GW);
    const int yx = pix % (GH * GW);
    const float* gp = guid + (size_t)b * 3 * GH * GW + yx;
    const float g0 = gp[0], g1 = gp[GH * GW], g2 = gp[2 * GH * GW];

    float u[32];
    #pragma unroll
    for (int k = 0; k < 32; k++) {
        float a = sb1[k] + sw1[k * 3] * g0 + sw1[k * 3 + 1] * g1 + sw1[k * 3 + 2] * g2;
        float c = a * (0.7978845608028654f + 0.035677408136300125f * a * a);
        float th;
        asm("tanh.approx.f32 %0, %1;" : "=f"(th) : "f"(c));
        u[k] = 0.5f * a * (1.f + th);
    }
    int uw[8];
    #pragma unroll
    for (int w = 0; w < 8; w++)
        uw[w] = pack4(u[4 * w], u[4 * w + 1], u[4 * w + 2], u[4 * w + 3], ru);

    float qf[32];
    float qmax = 1e-12f;
    #pragma unroll
    for (int j = 0; j < 32; j++) {
        int d = 0;
        #pragma unroll
        for (int i = 0; i < 8; i++) d = __dp4a(uw[i], sw2q[j][i], d);
        qf[j] = fmaf((float)d, us_ * ssc[j], sb2[j]);
        qmax = fmaxf(qmax, fabsf(qf[j]));
    }
    const float rq = 127.f / qmax;
    unsigned int ow[8];
    #pragma unroll
    for (int w = 0; w < 8; w++)
        ow[w] = (unsigned int)pack4(qf[4 * w], qf[4 * w + 1], qf[4 * w + 2], qf[4 * w + 3], rq);

    unsigned int* dst = g_q + ((size_t)s * NPIX + pix) * QW;
    *(uint4*)dst       = make_uint4(ow[0], ow[1], ow[2], ow[3]);
    *(uint4*)(dst + 4) = make_uint4(ow[4], ow[5], ow[6], ow[7]);
    dst[8] = __float_as_uint(qmax * (1.f / 127.f));
}

// ---------------------------------------------------------------------------
// L1: linear (blocks 0..971) + LUT/u-bound (972) + w2quant (973)
// ---------------------------------------------------------------------------
__global__ __launch_bounds__(256) void k_L1(
    const float* __restrict__ x, const float* __restrict__ W,
    const float* __restrict__ bias,
    const float* __restrict__ w1s, const float* __restrict__ b1s,
    const float* __restrict__ w2s)
{
    const int bid = blockIdx.x, tid = threadIdx.x;
    if (bid == NLIN_BLKS)     { init_lut_block(w1s, b1s, tid); return; }
    if (bid == NLIN_BLKS + 1) { init_w2_block(w2s, tid); return; }

    int gw = bid * 8 + (tid >> 5);
    int lane = tid & 31;
    if (gw >= NB * 972) return;
    int b = gw / 972, j = gw % 972;
    const float4* xr = (const float4*)(x + b * 1000);
    const float4* wr = (const float4*)(W + j * 1000);
    float acc = 0.f;
    for (int k = lane; k < 250; k += 32) {
        float4 xa = xr[k], wa = wr[k];
        acc += xa.x * wa.x + xa.y * wa.y + xa.z * wa.z + xa.w * wa.w;
    }
    #pragma unroll
    for (int o = 16; o; o >>= 1) acc += __shfl_xor_sync(0xffffffffu, acc, o);
    if (lane == 0) g_f0[gw] = acc + bias[j];
}

// ---------------------------------------------------------------------------
// L2: bicubic horizontal (blocks 0..377) + qproj stage 0
// ---------------------------------------------------------------------------
__global__ __launch_bounds__(256) void k_L2(
    const float* __restrict__ guid,
    const float* __restrict__ w1s, const float* __restrict__ b1s,
    const float* __restrict__ b2s)
{
    const int bid = blockIdx.x, tid = threadIdx.x;
    if (bid >= NBIC1_BLKS) {
        qproj_block(0, bid - NBIC1_BLKS, tid, guid, w1s, b1s, b2s);
        return;
    }
    int idx = bid * 256 + tid;        // 24*18*224 = 378*256 exact
    int xo = idx % 224;
    int r  = (idx / 224) % 18;
    int bc = idx / (224 * 18);
    float4 w = g_lutw[xo];
    int4 ix = g_luti[xo];
    const float* row = g_f0 + bc * 324 + r * 18;
    g_tmp[idx] = w.x * row[ix.x] + w.y * row[ix.y] + w.z * row[ix.z] + w.w * row[ix.w];
}

// ---------------------------------------------------------------------------
// L3: bicubic vertical -> interleaved float4 (blocks 0..1567) + qproj stage 1
// ---------------------------------------------------------------------------
__global__ __launch_bounds__(256) void k_L3(
    const float* __restrict__ guid,
    const float* __restrict__ w1s, const float* __restrict__ b1s,
    const float* __restrict__ b2s)
{
    const int bid = blockIdx.x, tid = threadIdx.x;
    if (bid >= NQ_BLKS) {
        qproj_block(1, bid - NQ_BLKS, tid, guid, w1s, b1s, b2s);
        return;
    }
    int pix = bid * 256 + tid;        // NPIX exact
    int xo = pix % 224;
    int yo = (pix / 224) % 224;
    int b  = pix / (224 * 224);
    float4 w = g_lutw[yo];
    int4 iy = g_luti[yo];
    float o[3];
    #pragma unroll
    for (int c = 0; c < 3; c++) {
        const float* t = g_tmp + (b * 3 + c) * 18 * 224 + xo;
        o[c] = w.x * t[iy.x * 224] + w.y * t[iy.y * 224]
             + w.z * t[iy.z * 224] + w.w * t[iy.w * 224];
    }
    g_bufA[pix] = make_float4(o[0], o[1], o[2], 0.f);
}

// ---------------------------------------------------------------------------
// K_stage: 32x32 tile JBU (blocks 0..391) + optional qproj backfill.
// srcI interleaved float4; output interleaved (or planar for final stage).
// ---------------------------------------------------------------------------
__global__ __launch_bounds__(256, 3) void k_stage(
    const float4* __restrict__ srcI, float4* __restrict__ dstI,
    float* __restrict__ dstP, int planar,
    const float* __restrict__ guid,
    const float* __restrict__ w1s, const float* __restrict__ b1s,
    const float* __restrict__ b2s,
    const float* __restrict__ temps, const float* __restrict__ sigmas, int s)
{
    extern __shared__ unsigned int shQ[];      // NHALO * 12 words
    const int tid = threadIdx.x;
    const int bid = blockIdx.x;

    if (bid >= NSTAGE_BLKS) {
        qproj_block(s + 2, bid - NSTAGE_BLKS, tid, guid, w1s, b1s, b2s);
        return;
    }

    const int b = bid / 49;
    const int rem = bid % 49;
    const int ty0 = (rem / 7) * TH, tx0 = (rem % 7) * TW;

    const unsigned int* qbase = g_q + (size_t)s * NPIX * QW;

    for (int hp = tid; hp < NHALO; hp += 256) {
        int yy = hp / HC, xx = hp % HC;
        int gy = reflect224(ty0 + yy - RAD);
        int gx = reflect224(tx0 + xx - RAD);
        int pix = b * (GH * GW) + gy * GW + gx;
        const unsigned int* qp = qbase + (size_t)pix * QW;
        unsigned int* qd = shQ + hp * QW;
        *(uint4*)qd       = *(const uint4*)qp;
        *(uint4*)(qd + 4) = *(const uint4*)(qp + 4);
        float4 sv = srcI[pix];
        *(float4*)(qd + 8) = make_float4(sv.x, sv.y, sv.z, __uint_as_float(qp[8]));
    }
    __syncthreads();

    const int ty = tid >> 5, tx = tid & 31;   // pixels (4ty + p, tx)

    float t = expf(temps[s]);
    t = fminf(fmaxf(t, 1e-4f), 1e4f);
    const float tl2e = t * LOG2E;

    int c[4][8];
    float pre[4];
    #pragma unroll
    for (int p = 0; p < 4; p++) {
        const unsigned int* cp = shQ + ((4 * ty + p + RAD) * HC + tx + RAD) * QW;
        *(uint4*)&c[p][0] = *(const uint4*)cp;
        *(uint4*)&c[p][4] = *(const uint4*)(cp + 4);
        pre[p] = tl2e * __uint_as_float(cp[11]);
    }

    const float sig = sigmas[s];
    const float inv2s = 1.f / (2.f * sig * sig);
    float le[7];
    #pragma unroll
    for (int i = 0; i < 7; i++) {
        float d = (i - 3) * (1.f / 3.f);
        le[i] = -d * d * inv2s * LOG2E;
    }

    float sum[4] = {0.f, 0.f, 0.f, 0.f};
    float o0[4] = {0.f, 0.f, 0.f, 0.f};
    float o1[4] = {0.f, 0.f, 0.f, 0.f};
    float o2[4] = {0.f, 0.f, 0.f, 0.f};

    #pragma unroll
    for (int dyp = 0; dyp < 10; dyp++) {
        const int r = 4 * ty + dyp;
        #pragma unroll
        for (int dx = 0; dx < 7; dx++) {
            const unsigned int* np = shQ + (r * HC + tx + dx) * QW;
            int n[8];
            *(uint4*)&n[0] = *(const uint4*)np;
            *(uint4*)&n[4] = *(const uint4*)(np + 4);
            const float4 ss = *(const float4*)(np + 8);
            #pragma unroll
            for (int p = 0; p < 4; p++) {
                if (dyp >= p && dyp < p + 7) {
                    int d0 = 0, d1 = 0;
                    #pragma unroll
                    for (int i = 0; i < 4; i++) {
                        d0 = __dp4a(c[p][i], n[i], d0);
                        d1 = __dp4a(c[p][i + 4], n[i + 4], d1);
                    }
                    float arg = fmaf(pre[p] * ss.w, (float)(d0 + d1), le[dyp - p] + le[dx]);
                    float w;
                    asm("ex2.approx.f32 %0, %1;" : "=f"(w) : "f"(arg));
                    sum[p] += w;
                    o0[p] += w * ss.x;
                    o1[p] += w * ss.y;
                    o2[p] += w * ss.z;
                }
            }
        }
    }

    const int ox = tx0 + tx;
    #pragma unroll
    for (int p = 0; p < 4; p++) {
        const float inv = 1.f / fmaxf(sum[p], 1e-30f);
        const int oy = ty0 + 4 * ty + p;
        if (planar) {
            float* dp = dstP + ((size_t)b * 3 * GH + oy) * GW + ox;
            dp[0]           = o0[p] * inv;
            dp[GH * GW]     = o1[p] * inv;
            dp[2 * GH * GW] = o2[p] * inv;
        } else {
            dstI[b * (GH * GW) + oy * GW + ox] =
                make_float4(o0[p] * inv, o1[p] * inv, o2[p] * inv, 0.f);
        }
    }
}

// ---------------------------------------------------------------------------
extern "C" void kernel_launch(void* const* d_in, const int* in_sizes, int n_in,
                              void* d_out, int out_size) {
    const float* x      = (const float*)d_in[0];
    const float* guid   = (const float*)d_in[1];
    const float* lw     = (const float*)d_in[2];
    const float* lb     = (const float*)d_in[3];
    const float* w1s    = (const float*)d_in[4];
    const float* b1s    = (const float*)d_in[5];
    const float* w2s    = (const float*)d_in[6];
    const float* b2s    = (const float*)d_in[7];
    const float* temps  = (const float*)d_in[8];
    const float* sigmas = (const float*)d_in[9];
    float* out = (float*)d_out;

    void *pa, *pb;
    cudaGetSymbolAddress(&pa, g_bufA);
    cudaGetSymbolAddress(&pb, g_bufB);
    float4* A  = (float4*)pa;
    float4* Bb = (float4*)pb;

    const int smem = NHALO * QW * 4;   // 69312 B
    cudaFuncSetAttribute(k_stage, cudaFuncAttributeMaxDynamicSharedMemorySize, smem);

    k_L1<<<NLIN_BLKS + 2, 256>>>(x, lw, lb, w1s, b1s, w2s);
    k_L2<<<NBIC1_BLKS + NQ_BLKS, 256>>>(guid, w1s, b1s, b2s);          // bic1 + qproj0
    k_L3<<<NQ_BLKS + NQ_BLKS, 256>>>(guid, w1s, b1s, b2s);             // bic2 + qproj1
    // stage s (+ qproj s+2 backfill for s=0,1)
    k_stage<<<NSTAGE_BLKS + NQ_BLKS, 256, smem>>>(A,  Bb, out, 0, guid, w1s, b1s, b2s, temps, sigmas, 0);
    k_stage<<<NSTAGE_BLKS + NQ_BLKS, 256, smem>>>(Bb, A,  out, 0, guid, w1s, b1s, b2s, temps, sigmas, 1);
    k_stage<<<NSTAGE_BLKS, 256, smem>>>(A,  Bb, out, 0, guid, w1s, b1s, b2s, temps, sigmas, 2);
    k_stage<<<NSTAGE_BLKS, 256, smem>>>(Bb, A,  out, 1, guid, w1s, b1s, b2s, temps, sigmas, 3);
}

// round 15
// speedup vs baseline: 1.0295x; 1.0295x over previous
#include <cuda_runtime.h>
#include <cuda_fp16.h>
#include <math.h>

#define NB   8
#define GH   224
#define GW   224
#define RAD  3
#define TW   32
#define TH   32
#define HC   38
#define HR   38
#define NHALO (HR * HC)  // 1444
#define NPIX (NB * GH * GW)          // 401408
#define QW   12
#define LOG2E 1.4426950408889634f
#define NSTAGE_BLKS 392              // 7 x 7 x 8 tiles
#define NQ_BLKS     1568             // NPIX / 256
#define NLIN_BLKS   972
#define NBIC1_BLKS  378              // 24*18*224 / 256
#define NBIC2_BLKS  1568             // NPIX / 256

// scratch (no allocations allowed)
__device__ float g_f0[NB * 972];
__device__ __align__(16) float g_tmp[24 * 18 * 224];
__device__ __align__(16) float4 g_bufA[NPIX];   // interleaved {f0,f1,f2,_}
__device__ __align__(16) float4 g_bufB[NPIX];
// q maps, SoA for coalesced stores: per stage,pixel
__device__ __align__(16) uint4 g_qa[4 * NPIX];
__device__ __align__(16) uint4 g_qb[4 * NPIX];
__device__ float g_qs[4 * NPIX];
__device__ int g_w2q[4 * 32 * 8];
__device__ float g_w2s[4 * 32];
__device__ float g_us[4];
__device__ float4 g_lutw[224];
__device__ int4   g_luti[224];

__device__ __forceinline__ int reflect224(int v) {
    if (v < 0) v = -v;
    if (v > 223) v = 446 - v;
    return v;
}

__device__ __forceinline__ float cubw(float d) {
    d = fabsf(d);
    if (d <= 1.f) return (1.25f * d - 2.25f) * d * d + 1.f;
    if (d < 2.f)  return ((-0.75f * d + 3.75f) * d - 6.f) * d + 3.f;
    return 0.f;
}

__device__ __forceinline__ int pack4(float a, float b, float c, float d, float rs) {
    int i0 = __float2int_rn(a * rs);
    int i1 = __float2int_rn(b * rs);
    int i2 = __float2int_rn(c * rs);
    int i3 = __float2int_rn(d * rs);
    return (i0 & 255) | ((i1 & 255) << 8) | ((i2 & 255) << 16) | (i3 << 24);
}

// ---------------------------------------------------------------------------
// init roles (inside L1 launch)
// ---------------------------------------------------------------------------
__device__ void init_lut_block(const float* w1s_, const float* b1s_, int tid) {
    if (tid < 224) {
        float fx = (tid + 0.5f) * (18.f / 224.f) - 0.5f;
        int x0 = (int)floorf(fx);
        float tx = fx - x0;
        float4 w; int4 ix;
        w.x = cubw(tx + 1.f); w.y = cubw(tx); w.z = cubw(tx - 1.f); w.w = cubw(tx - 2.f);
        ix.x = min(max(x0 - 1, 0), 17); ix.y = min(max(x0, 0), 17);
        ix.z = min(max(x0 + 1, 0), 17); ix.w = min(max(x0 + 2, 0), 17);
        g_lutw[tid] = w; g_luti[tid] = ix;
    } else if (tid >= 224 && tid < 228) {
        int s = tid - 224;
        float ub = 0.2f;
        for (int k = 0; k < 32; k++) {
            float bnd = fabsf(b1s_[s * 32 + k]);
            for (int c = 0; c < 3; c++) bnd += fabsf(w1s_[s * 96 + k * 3 + c]);
            ub = fmaxf(ub, bnd);
        }
        g_us[s] = ub;
    }
}

__device__ void init_w2_block(const float* w2s_, int tid) {
    if (tid >= 128) return;
    int r = tid;
    const float* row = w2s_ + r * 32;
    float mx = 1e-12f;
    #pragma unroll
    for (int k = 0; k < 32; k++) mx = fmaxf(mx, fabsf(row[k]));
    float rs = 127.f / mx;
    #pragma unroll
    for (int w = 0; w < 8; w++)
        g_w2q[r * 8 + w] = pack4(row[4 * w], row[4 * w + 1], row[4 * w + 2], row[4 * w + 3], rs);
    g_w2s[r] = mx * (1.f / 127.f);
}

// ---------------------------------------------------------------------------
// qproj block: 256 px, int8 dp4a matvec, SoA coalesced output
// ---------------------------------------------------------------------------
__device__ __forceinline__ void qproj_block(
    int s, int qbid, int tid,
    const float* __restrict__ guid,
    const float* __restrict__ w1s, const float* __restrict__ b1s,
    const float* __restrict__ b2s)
{
    __shared__ float sw1[96];
    __shared__ float sb1[32];
    __shared__ float sb2[32];
    __shared__ float ssc[32];
    __shared__ int sw2q[32][8];

    if (tid < 96) sw1[tid] = w1s[s * 96 + tid];
    if (tid < 32) {
        sb1[tid] = b1s[s * 32 + tid];
        sb2[tid] = b2s[s * 32 + tid];
        ssc[tid] = g_w2s[s * 32 + tid];
    }
    sw2q[tid >> 3][tid & 7] = g_w2q[(s * 32 + (tid >> 3)) * 8 + (tid & 7)];
    __syncthreads();

    const float uscale = g_us[s];
    const float ru = 127.f / uscale;
    const float us_ = uscale * (1.f / 127.f);

    const int pix = qbid * 256 + tid;
    const int b = pix / (GH * GW);
    const int yx = pix % (GH * GW);
    const float* gp = guid + (size_t)b * 3 * GH * GW + yx;
    const float g0 = gp[0], g1 = gp[GH * GW], g2 = gp[2 * GH * GW];

    float u[32];
    #pragma unroll
    for (int k = 0; k < 32; k++) {
        float a = sb1[k] + sw1[k * 3] * g0 + sw1[k * 3 + 1] * g1 + sw1[k * 3 + 2] * g2;
        float c = a * (0.7978845608028654f + 0.035677408136300125f * a * a);
        float th;
        asm("tanh.approx.f32 %0, %1;" : "=f"(th) : "f"(c));
        u[k] = 0.5f * a * (1.f + th);
    }
    int uw[8];
    #pragma unroll
    for (int w = 0; w < 8; w++)
        uw[w] = pack4(u[4 * w], u[4 * w + 1], u[4 * w + 2], u[4 * w + 3], ru);

    float qf[32];
    float qmax = 1e-12f;
    #pragma unroll
    for (int j = 0; j < 32; j++) {
        uint4 w0 = *(const uint4*)&sw2q[j][0];
        uint4 w1v = *(const uint4*)&sw2q[j][4];
        int d = 0;
        d = __dp4a(uw[0], (int)w0.x, d);  d = __dp4a(uw[1], (int)w0.y, d);
        d = __dp4a(uw[2], (int)w0.z, d);  d = __dp4a(uw[3], (int)w0.w, d);
        d = __dp4a(uw[4], (int)w1v.x, d); d = __dp4a(uw[5], (int)w1v.y, d);
        d = __dp4a(uw[6], (int)w1v.z, d); d = __dp4a(uw[7], (int)w1v.w, d);
        qf[j] = fmaf((float)d, us_ * ssc[j], sb2[j]);
        qmax = fmaxf(qmax, fabsf(qf[j]));
    }
    const float rq = 127.f / qmax;
    unsigned int ow[8];
    #pragma unroll
    for (int w = 0; w < 8; w++)
        ow[w] = (unsigned int)pack4(qf[4 * w], qf[4 * w + 1], qf[4 * w + 2], qf[4 * w + 3], rq);

    const int gidx = s * NPIX + pix;
    g_qa[gidx] = make_uint4(ow[0], ow[1], ow[2], ow[3]);
    g_qb[gidx] = make_uint4(ow[4], ow[5], ow[6], ow[7]);
    g_qs[gidx] = qmax * (1.f / 127.f);
}

// ---------------------------------------------------------------------------
// L1: linear (blocks 0..971) + LUT/u-bound (972) + w2quant (973)
// ---------------------------------------------------------------------------
__global__ __launch_bounds__(256) void k_L1(
    const float* __restrict__ x, const float* __restrict__ W,
    const float* __restrict__ bias,
    const float* __restrict__ w1s, const float* __restrict__ b1s,
    const float* __restrict__ w2s)
{
    const int bid = blockIdx.x, tid = threadIdx.x;
    if (bid == NLIN_BLKS)     { init_lut_block(w1s, b1s, tid); return; }
    if (bid == NLIN_BLKS + 1) { init_w2_block(w2s, tid); return; }

    int gw = bid * 8 + (tid >> 5);
    int lane = tid & 31;
    if (gw >= NB * 972) return;
    int b = gw / 972, j = gw % 972;
    const float4* xr = (const float4*)(x + b * 1000);
    const float4* wr = (const float4*)(W + j * 1000);
    float acc = 0.f;
    for (int k = lane; k < 250; k += 32) {
        float4 xa = xr[k], wa = wr[k];
        acc += xa.x * wa.x + xa.y * wa.y + xa.z * wa.z + xa.w * wa.w;
    }
    #pragma unroll
    for (int o = 16; o; o >>= 1) acc += __shfl_xor_sync(0xffffffffu, acc, o);
    if (lane == 0) g_f0[gw] = acc + bias[j];
}

// ---------------------------------------------------------------------------
// L2: qproj for ALL 4 stages (blocks 0..6271) + bicubic horizontal (rest)
// Small-smem launch -> qproj runs at its reg-limited 4 blocks/SM.
// ---------------------------------------------------------------------------
__global__ __launch_bounds__(256) void k_L2(
    const float* __restrict__ guid,
    const float* __restrict__ w1s, const float* __restrict__ b1s,
    const float* __restrict__ b2s)
{
    const int bid = blockIdx.x, tid = threadIdx.x;
    if (bid < 4 * NQ_BLKS) {
        qproj_block(bid / NQ_BLKS, bid % NQ_BLKS, tid, guid, w1s, b1s, b2s);
        return;
    }
    int idx = (bid - 4 * NQ_BLKS) * 256 + tid;   // 24*18*224 = 378*256 exact
    int xo = idx % 224;
    int r  = (idx / 224) % 18;
    int bc = idx / (224 * 18);
    float4 w = g_lutw[xo];
    int4 ix = g_luti[xo];
    const float* row = g_f0 + bc * 324 + r * 18;
    g_tmp[idx] = w.x * row[ix.x] + w.y * row[ix.y] + w.z * row[ix.z] + w.w * row[ix.w];
}

// ---------------------------------------------------------------------------
// L3: bicubic vertical -> interleaved float4
// ---------------------------------------------------------------------------
__global__ __launch_bounds__(256) void k_L3() {
    int pix = blockIdx.x * 256 + threadIdx.x;    // NPIX exact
    int xo = pix % 224;
    int yo = (pix / 224) % 224;
    int b  = pix / (224 * 224);
    float4 w = g_lutw[yo];
    int4 iy = g_luti[yo];
    float o[3];
    #pragma unroll
    for (int c = 0; c < 3; c++) {
        const float* t = g_tmp + (b * 3 + c) * 18 * 224 + xo;
        o[c] = w.x * t[iy.x * 224] + w.y * t[iy.y * 224]
             + w.z * t[iy.z * 224] + w.w * t[iy.w * 224];
    }
    g_bufA[pix] = make_float4(o[0], o[1], o[2], 0.f);
}

// ---------------------------------------------------------------------------
// K_stage: pure 32x32 tile JBU, 4 vertical px/thread, f32x2 accumulators.
// ---------------------------------------------------------------------------
__global__ __launch_bounds__(256, 3) void k_stage(
    const float4* __restrict__ srcI, float4* __restrict__ dstI,
    float* __restrict__ dstP, int planar,
    const float* __restrict__ temps, const float* __restrict__ sigmas, int s)
{
    extern __shared__ unsigned int shQ[];      // NHALO * 12 words
    const int tid = threadIdx.x;
    const int bid = blockIdx.x;

    const int b = bid / 49;
    const int rem = bid % 49;
    const int ty0 = (rem / 7) * TH, tx0 = (rem % 7) * TW;

    const int qoff = s * NPIX;

    for (int hp = tid; hp < NHALO; hp += 256) {
        int yy = hp / HC, xx = hp % HC;
        int gy = reflect224(ty0 + yy - RAD);
        int gx = reflect224(tx0 + xx - RAD);
        int pix = b * (GH * GW) + gy * GW + gx;
        unsigned int* qd = shQ + hp * QW;
        *(uint4*)qd       = g_qa[qoff + pix];
        *(uint4*)(qd + 4) = g_qb[qoff + pix];
        float4 sv = srcI[pix];
        *(float4*)(qd + 8) = make_float4(sv.x, sv.y, sv.z, g_qs[qoff + pix]);
    }
    __syncthreads();

    const int ty = tid >> 5, tx = tid & 31;   // pixels (4ty + p, tx)

    float t = expf(temps[s]);
    t = fminf(fmaxf(t, 1e-4f), 1e4f);
    const float tl2e = t * LOG2E;

    int c[4][8];
    float pre[4];
    #pragma unroll
    for (int p = 0; p < 4; p++) {
        const unsigned int* cp = shQ + ((4 * ty + p + RAD) * HC + tx + RAD) * QW;
        *(uint4*)&c[p][0] = *(const uint4*)cp;
        *(uint4*)&c[p][4] = *(const uint4*)(cp + 4);
        pre[p] = tl2e * __uint_as_float(cp[11]);
    }

    const float sig = sigmas[s];
    const float inv2s = 1.f / (2.f * sig * sig);
    float le[7];
    #pragma unroll
    for (int i = 0; i < 7; i++) {
        float d = (i - 3) * (1.f / 3.f);
        le[i] = -d * d * inv2s * LOG2E;
    }
    const float fone = 1.0f;

    // packed accumulators: a01 = {o0,o1}, a2s = {o2,sum}
    unsigned long long a01[4], a2s[4];
    #pragma unroll
    for (int p = 0; p < 4; p++) { a01[p] = 0ull; a2s[p] = 0ull; }

    #pragma unroll
    for (int dyp = 0; dyp < 10; dyp++) {
        const int r = 4 * ty + dyp;
        #pragma unroll
        for (int dx = 0; dx < 7; dx++) {
            const unsigned int* np = shQ + (r * HC + tx + dx) * QW;
            int n[8];
            *(uint4*)&n[0] = *(const uint4*)np;
            *(uint4*)&n[4] = *(const uint4*)(np + 4);
            const float4 ss = *(const float4*)(np + 8);
            unsigned long long ss01, ss2s;
            asm("mov.b64 %0, {%1,%2};" : "=l"(ss01) : "f"(ss.x), "f"(ss.y));
            asm("mov.b64 %0, {%1,%2};" : "=l"(ss2s) : "f"(ss.z), "f"(fone));
            #pragma unroll
            for (int p = 0; p < 4; p++) {
                if (dyp >= p && dyp < p + 7) {
                    int d0 = 0, d1 = 0;
                    #pragma unroll
                    for (int i = 0; i < 4; i++) {
                        d0 = __dp4a(c[p][i], n[i], d0);
                        d1 = __dp4a(c[p][i + 4], n[i + 4], d1);
                    }
                    float arg = fmaf(pre[p] * ss.w, (float)(d0 + d1), le[dyp - p] + le[dx]);
                    float w;
                    asm("ex2.approx.f32 %0, %1;" : "=f"(w) : "f"(arg));
                    unsigned long long ww;
                    asm("mov.b64 %0, {%1,%1};" : "=l"(ww) : "f"(w));
                    asm("fma.rn.f32x2 %0, %1, %2, %3;" : "=l"(a01[p]) : "l"(ww), "l"(ss01), "l"(a01[p]));
                    asm("fma.rn.f32x2 %0, %1, %2, %3;" : "=l"(a2s[p]) : "l"(ww), "l"(ss2s), "l"(a2s[p]));
                }
            }
        }
    }

    const int ox = tx0 + tx;
    #pragma unroll
    for (int p = 0; p < 4; p++) {
        float o0, o1, o2, sum;
        asm("mov.b64 {%0,%1}, %2;" : "=f"(o0), "=f"(o1) : "l"(a01[p]));
        asm("mov.b64 {%0,%1}, %2;" : "=f"(o2), "=f"(sum) : "l"(a2s[p]));
        const float inv = 1.f / fmaxf(sum, 1e-30f);
        const int oy = ty0 + 4 * ty + p;
        if (planar) {
            float* dp = dstP + ((size_t)b * 3 * GH + oy) * GW + ox;
            dp[0]           = o0 * inv;
            dp[GH * GW]     = o1 * inv;
            dp[2 * GH * GW] = o2 * inv;
        } else {
            dstI[b * (GH * GW) + oy * GW + ox] =
                make_float4(o0 * inv, o1 * inv, o2 * inv, 0.f);
        }
    }
}

// ---------------------------------------------------------------------------
extern "C" void kernel_launch(void* const* d_in, const int* in_sizes, int n_in,
                              void* d_out, int out_size) {
    const float* x      = (const float*)d_in[0];
    const float* guid   = (const float*)d_in[1];
    const float* lw     = (const float*)d_in[2];
    const float* lb     = (const float*)d_in[3];
    const float* w1s    = (const float*)d_in[4];
    const float* b1s    = (const float*)d_in[5];
    const float* w2s    = (const float*)d_in[6];
    const float* b2s    = (const float*)d_in[7];
    const float* temps  = (const float*)d_in[8];
    const float* sigmas = (const float*)d_in[9];
    float* out = (float*)d_out;

    void *pa, *pb;
    cudaGetSymbolAddress(&pa, g_bufA);
    cudaGetSymbolAddress(&pb, g_bufB);
    float4* A  = (float4*)pa;
    float4* Bb = (float4*)pb;

    const int smem = NHALO * QW * 4;   // 69312 B
    cudaFuncSetAttribute(k_stage, cudaFuncAttributeMaxDynamicSharedMemorySize, smem);

    k_L1<<<NLIN_BLKS + 2, 256>>>(x, lw, lb, w1s, b1s, w2s);
    k_L2<<<4 * NQ_BLKS + NBIC1_BLKS, 256>>>(guid, w1s, b1s, b2s);  // qproj x4 + bic1
    k_L3<<<NBIC2_BLKS, 256>>>();                                    // bic2
    k_stage<<<NSTAGE_BLKS, 256, smem>>>(A,  Bb, out, 0, temps, sigmas, 0);
    k_stage<<<NSTAGE_BLKS, 256, smem>>>(Bb, A,  out, 0, temps, sigmas, 1);
    k_stage<<<NSTAGE_BLKS, 256, smem>>>(A,  Bb, out, 0, temps, sigmas, 2);
    k_stage<<<NSTAGE_BLKS, 256, smem>>>(Bb, A,  out, 1, temps, sigmas, 3);
}